// round 16
// baseline (speedup 1.0000x reference)
#include <cuda_runtime.h>
#include <cuda_fp16.h>
#include <cstdint>

#define CUT0   2000
#define CUT1   20000
#define BATCH  8192
#define HDIM   1024
#define H4     256
#define NCOLS0 18000
#define NCOLS1 30000
#define HEADC  2002

#define BM 128
#define BN 128
#define BK 32
#define LDS 40                 // halves per smem row (32 + 8 pad)
#define OPBYTES 10240          // 128*40*2
#define BUFBYTES 30720         // 3 operand tiles (Ah, Al, Bh)
#define NSTAGE 3
#define SMEM_BYTES 92160       // 3 stages; 2 CTAs/SM -> 184320 <= 228KB

// ---------------- device scratch (no allocations allowed) ----------------
__device__ int d_idx0[BATCH];
__device__ int d_idx1[BATCH];
__device__ int d_counts[2];

__device__ __half g_hidh[BATCH * HDIM],  g_hidl[BATCH * HDIM];
__device__ __half g_embh[50000 * HDIM];
__device__ __half g_d0h[HDIM * HDIM];
__device__ __half g_d1h[H4 * HDIM];
__device__ __half g_dec0h[NCOLS0 * HDIM];
__device__ __half g_dec1h[NCOLS1 * H4];
__device__ __half g_h0h[BATCH * HDIM];
__device__ __half g_h1h[BATCH * H4];

// ---------------- PTX helpers --------------------------------------------
__device__ __forceinline__ uint32_t smem_u32(const void* p) {
    uint32_t a;
    asm("{ .reg .u64 t; cvta.to.shared.u64 t, %1; cvt.u32.u64 %0, t; }"
        : "=r"(a) : "l"(p));
    return a;
}
#define CPA(dst, src) \
    asm volatile("cp.async.cg.shared.global [%0], [%1], 16;" \
                 :: "r"(dst), "l"(src) : "memory")
#define CPA_COMMIT() asm volatile("cp.async.commit_group;" ::: "memory")
#define CPA_WAIT(n)  asm volatile("cp.async.wait_group %0;" :: "n"(n) : "memory")

#define LDSM4(r, addr) \
    asm volatile("ldmatrix.sync.aligned.m8n8.x4.shared.b16 {%0,%1,%2,%3}, [%4];" \
                 : "=r"((r)[0]), "=r"((r)[1]), "=r"((r)[2]), "=r"((r)[3]) \
                 : "r"(addr))

#define MMA_FP16(c, a, b0, b1) \
    asm volatile("mma.sync.aligned.m16n8k16.row.col.f32.f16.f16.f32 " \
                 "{%0,%1,%2,%3}, {%4,%5,%6,%7}, {%8,%9}, {%0,%1,%2,%3};" \
                 : "+f"((c)[0]), "+f"((c)[1]), "+f"((c)[2]), "+f"((c)[3]) \
                 : "r"((a)[0]), "r"((a)[1]), "r"((a)[2]), "r"((a)[3]), \
                   "r"(b0), "r"(b1))

// ---------------- partition targets (int32/int64 agnostic) ---------------
__global__ void scan_targets_kernel(const int* __restrict__ tw) {
    __shared__ int s0[1024], s1[1024];
    __shared__ int anynz;
    int t = threadIdx.x;
    if (t == 0) anynz = 0;
    __syncthreads();
    int nz = 0;
    for (int i = t; i < 4096; i += 1024) nz |= (tw[2 * i + 1] != 0);
    if (nz) atomicOr(&anynz, 1);
    __syncthreads();
    int stride = anynz ? 1 : 2;

    int v[8]; int c0 = 0, c1 = 0;
#pragma unroll
    for (int i = 0; i < 8; i++) {
        v[i] = tw[(t * 8 + i) * stride];
        c0 += (v[i] >= CUT0 && v[i] < CUT1) ? 1 : 0;
        c1 += (v[i] >= CUT1) ? 1 : 0;
    }
    s0[t] = c0; s1[t] = c1;
    __syncthreads();
    for (int off = 1; off < 1024; off <<= 1) {
        int a0 = (t >= off) ? s0[t - off] : 0;
        int a1 = (t >= off) ? s1[t - off] : 0;
        __syncthreads();
        s0[t] += a0; s1[t] += a1;
        __syncthreads();
    }
    int p0 = s0[t] - c0, p1 = s1[t] - c1;
#pragma unroll
    for (int i = 0; i < 8; i++) {
        if (v[i] >= CUT0 && v[i] < CUT1)      d_idx0[p0++] = t * 8 + i;
        else if (v[i] >= CUT1)                d_idx1[p1++] = t * 8 + i;
    }
    if (t == 1023) { d_counts[0] = s0[1023]; d_counts[1] = s1[1023]; }
}

// ---------------- fp32 -> fp16 hi(+lo) conversions ------------------------
__global__ void conv_pair_kernel(const float4* __restrict__ src,
                                 __half* __restrict__ hi,
                                 __half* __restrict__ lo, int n4) {
    int i = blockIdx.x * blockDim.x + threadIdx.x;
    int stride = gridDim.x * blockDim.x;
    for (; i < n4; i += stride) {
        float4 v = src[i];
        __half h0 = __float2half(v.x), h1 = __float2half(v.y);
        __half h2 = __float2half(v.z), h3 = __float2half(v.w);
        __half l0 = __float2half(v.x - __half2float(h0));
        __half l1 = __float2half(v.y - __half2float(h1));
        __half l2 = __float2half(v.z - __half2float(h2));
        __half l3 = __float2half(v.w - __half2float(h3));
        __half2* ph = (__half2*)(hi + (size_t)i * 4);
        __half2* pl = (__half2*)(lo + (size_t)i * 4);
        ph[0] = __halves2half2(h0, h1); ph[1] = __halves2half2(h2, h3);
        pl[0] = __halves2half2(l0, l1); pl[1] = __halves2half2(l2, l3);
    }
}

__global__ void conv_hi_kernel(const float4* __restrict__ src,
                               __half* __restrict__ hi, int n4) {
    int i = blockIdx.x * blockDim.x + threadIdx.x;
    int stride = gridDim.x * blockDim.x;
    for (; i < n4; i += stride) {
        float4 v = src[i];
        __half2* ph = (__half2*)(hi + (size_t)i * 4);
        ph[0] = __halves2half2(__float2half(v.x), __float2half(v.y));
        ph[1] = __halves2half2(__float2half(v.z), __float2half(v.w));
    }
}

// ---------------- HMMA split-fp16 GEMM: C = A @ B^T (+bias) --------------
// Al != nullptr: 2-pass (Ah*Bh + Al*Bh = A*fp16(B)); Al == nullptr: 1-pass.
// CTA tile 128x128xBK32, 256 threads, warps 4(M)x2(N), warp tile 32x64.
// 3-stage cp.async pipeline.
__global__ void __launch_bounds__(256, 2) hmma_gemm_kernel(
    const __half* __restrict__ Ah, const __half* __restrict__ Al,
    const int* __restrict__ rowidx,
    const __half* __restrict__ Bh,
    int N, int K,
    float* __restrict__ Cf, long long coff, int add_n0_off, int ldc,
    const float* __restrict__ bias,
    __half* __restrict__ Chi,
    int Mstatic, int msel)
{
    int M = (msel == 0) ? Mstatic : d_counts[msel - 1];
    int brow0 = blockIdx.y * BM;
    if (brow0 >= M) return;
    int bcol0 = blockIdx.x * BN;

    extern __shared__ char smem[];
    uint32_t sbase = smem_u32(smem);
    int tid = threadIdx.x, lane = tid & 31, wid = tid >> 5;
    int m0w = (wid >> 1) * 32, n0w = (wid & 1) * 64;
    bool twop = (Al != nullptr);

    // ---- gmem load plan: 2 units/thread per operand ----------------------
    int u1 = tid, u2 = tid + 256;
    int r1 = u1 >> 2, kq1 = u1 & 3, r2 = u2 >> 2, kq2 = u2 & 3;
    int ga1 = brow0 + r1; if (ga1 >= M) ga1 = M - 1;
    int ga2 = brow0 + r2; if (ga2 >= M) ga2 = M - 1;
    if (rowidx) { ga1 = rowidx[ga1]; ga2 = rowidx[ga2]; }
    int gb1 = bcol0 + r1; if (gb1 >= N) gb1 = N - 1;
    int gb2 = bcol0 + r2; if (gb2 >= N) gb2 = N - 1;
    const __half* Alz = twop ? Al : Ah;
    const __half* pA1h = Ah + (size_t)ga1 * K + kq1 * 8;
    const __half* pA1l = Alz + (size_t)ga1 * K + kq1 * 8;
    const __half* pB1h = Bh + (size_t)gb1 * K + kq1 * 8;
    const __half* pA2h = Ah + (size_t)ga2 * K + kq2 * 8;
    const __half* pA2l = Alz + (size_t)ga2 * K + kq2 * 8;
    const __half* pB2h = Bh + (size_t)gb2 * K + kq2 * 8;
    uint32_t sm1 = (uint32_t)(r1 * LDS + kq1 * 8) * 2;
    uint32_t sm2 = (uint32_t)(r2 * LDS + kq2 * 8) * 2;

    float acc[2][8][4];
#pragma unroll
    for (int mi = 0; mi < 2; mi++)
#pragma unroll
        for (int nf = 0; nf < 8; nf++)
#pragma unroll
            for (int e = 0; e < 4; e++) acc[mi][nf][e] = 0.f;

    int NCk = K >> 5;

#define ISSUE_STAGE(st, k0)                                                    \
    do {                                                                       \
        uint32_t b_ = sbase + (uint32_t)(st) * BUFBYTES;                       \
        CPA(b_ + 0 * OPBYTES + sm1, pA1h + (k0));                              \
        CPA(b_ + 0 * OPBYTES + sm2, pA2h + (k0));                              \
        if (twop) {                                                            \
            CPA(b_ + 1 * OPBYTES + sm1, pA1l + (k0));                          \
            CPA(b_ + 1 * OPBYTES + sm2, pA2l + (k0));                          \
        }                                                                      \
        CPA(b_ + 2 * OPBYTES + sm1, pB1h + (k0));                              \
        CPA(b_ + 2 * OPBYTES + sm2, pB2h + (k0));                              \
        CPA_COMMIT();                                                          \
    } while (0)

    ISSUE_STAGE(0, 0);
    if (NCk > 1) ISSUE_STAGE(1, BK);

    int lrow = lane & 15, lk = (lane >> 4) * 8;

    for (int c = 0; c < NCk; c++) {
        if (c + 2 < NCk) {
            ISSUE_STAGE((c + 2) % NSTAGE, (c + 2) * BK);
            CPA_WAIT(2);
        } else if (c + 1 < NCk) {
            CPA_WAIT(1);
        } else {
            CPA_WAIT(0);
        }
        __syncthreads();

        uint32_t buf = sbase + (uint32_t)(c % NSTAGE) * BUFBYTES;
#pragma unroll
        for (int ki = 0; ki < 2; ki++) {
            uint32_t koffb = (uint32_t)(ki * 16 + lk) * 2;
            uint32_t ah[2][4], al[2][4];
#pragma unroll
            for (int mi = 0; mi < 2; mi++) {
                uint32_t ro = (uint32_t)((m0w + mi * 16 + lrow) * LDS) * 2 + koffb;
                LDSM4(ah[mi], buf + 0 * OPBYTES + ro);
                if (twop) LDSM4(al[mi], buf + 1 * OPBYTES + ro);
            }
#pragma unroll
            for (int np = 0; np < 4; np++) {
                uint32_t ro = (uint32_t)((n0w + np * 16 + lrow) * LDS) * 2 + koffb;
                uint32_t bh[4];
                LDSM4(bh, buf + 2 * OPBYTES + ro);
#pragma unroll
                for (int mi = 0; mi < 2; mi++) {
                    MMA_FP16(acc[mi][np * 2],     ah[mi], bh[0], bh[2]);
                    MMA_FP16(acc[mi][np * 2 + 1], ah[mi], bh[1], bh[3]);
                }
                if (twop) {
#pragma unroll
                    for (int mi = 0; mi < 2; mi++) {
                        MMA_FP16(acc[mi][np * 2],     al[mi], bh[0], bh[2]);
                        MMA_FP16(acc[mi][np * 2 + 1], al[mi], bh[1], bh[3]);
                    }
                }
            }
        }
        __syncthreads();
    }

    // ---- epilogue ---------------------------------------------------------
    float* Cdst = Cf ? (Cf + coff +
        (add_n0_off ? (long long)d_counts[0] * (long long)NCOLS0 : 0ll)) : nullptr;
#pragma unroll
    for (int mi = 0; mi < 2; mi++) {
        int m = brow0 + m0w + mi * 16 + (lane >> 2);
#pragma unroll
        for (int nf = 0; nf < 8; nf++) {
            int n = bcol0 + n0w + nf * 8 + (lane & 3) * 2;
            if (n >= N) continue;
            float v0 = acc[mi][nf][0], v1 = acc[mi][nf][1];
            float v2 = acc[mi][nf][2], v3 = acc[mi][nf][3];
            if (Cdst) {
                float b0 = bias ? bias[n] : 0.f, b1 = bias ? bias[n + 1] : 0.f;
                if (m < M)
                    *(float2*)(Cdst + (size_t)m * ldc + n) = make_float2(v0 + b0, v1 + b1);
                if (m + 8 < M)
                    *(float2*)(Cdst + (size_t)(m + 8) * ldc + n) = make_float2(v2 + b0, v3 + b1);
            } else {
                if (m < M)
                    *(__half2*)(Chi + (size_t)m * ldc + n) =
                        __halves2half2(__float2half(v0), __float2half(v1));
                if (m + 8 < M)
                    *(__half2*)(Chi + (size_t)(m + 8) * ldc + n) =
                        __halves2half2(__float2half(v2), __float2half(v3));
            }
        }
    }
}

// -------- head tail columns: out[:, 2000:2002] ----------------------------
__global__ void head_tail_kernel(const float* __restrict__ hidden,
                                 const float* __restrict__ tw,
                                 const float* __restrict__ tb,
                                 float* __restrict__ out) {
    int row  = blockIdx.x * 4 + (threadIdx.x >> 5);
    int lane = threadIdx.x & 31;
    const float* h = hidden + (size_t)row * HDIM;
    float s0 = 0.f, s1 = 0.f;
    for (int i = lane; i < HDIM; i += 32) {
        float x = h[i];
        s0 += x * tw[i];
        s1 += x * tw[HDIM + i];
    }
#pragma unroll
    for (int o = 16; o > 0; o >>= 1) {
        s0 += __shfl_xor_sync(0xffffffffu, s0, o);
        s1 += __shfl_xor_sync(0xffffffffu, s1, o);
    }
    if (lane == 0) {
        out[(size_t)row * HEADC + CUT0]     = s0 + tb[0];
        out[(size_t)row * HEADC + CUT0 + 1] = s1 + tb[1];
    }
}

extern "C" void kernel_launch(void* const* d_in, const int* in_sizes, int n_in,
                              void* d_out, int out_size)
{
    (void)in_sizes; (void)n_in; (void)out_size;
    const float* hidden = (const float*)d_in[0];
    const float* embed  = (const float*)d_in[1];
    const float* tailW  = (const float*)d_in[2];
    const float* tailb  = (const float*)d_in[3];
    const float* sbias  = (const float*)d_in[4];
    const float* bias0  = (const float*)d_in[5];
    const float* bias1  = (const float*)d_in[6];
    const float* down0  = (const float*)d_in[7];
    const float* down1  = (const float*)d_in[8];
    const int*   targets = (const int*)d_in[9];
    float* out = (float*)d_out;

    __half *hidh, *hidl, *embh, *d0h, *d1h;
    __half *dec0h, *dec1h, *h0h, *h1h;
    int *idx0, *idx1;
    cudaGetSymbolAddress((void**)&hidh, g_hidh);  cudaGetSymbolAddress((void**)&hidl, g_hidl);
    cudaGetSymbolAddress((void**)&embh, g_embh);
    cudaGetSymbolAddress((void**)&d0h, g_d0h);    cudaGetSymbolAddress((void**)&d1h, g_d1h);
    cudaGetSymbolAddress((void**)&dec0h, g_dec0h); cudaGetSymbolAddress((void**)&dec1h, g_dec1h);
    cudaGetSymbolAddress((void**)&h0h, g_h0h);    cudaGetSymbolAddress((void**)&h1h, g_h1h);
    cudaGetSymbolAddress((void**)&idx0, d_idx0);  cudaGetSymbolAddress((void**)&idx1, d_idx1);

    static bool init_done = false;
    static cudaStream_t s1, s2, s3;
    static cudaEvent_t eFork, evHid, evScan, e1, e2, e3;
    if (!init_done) {
        cudaFuncSetAttribute(hmma_gemm_kernel,
                             cudaFuncAttributeMaxDynamicSharedMemorySize, SMEM_BYTES);
        cudaStreamCreateWithFlags(&s1, cudaStreamNonBlocking);
        cudaStreamCreateWithFlags(&s2, cudaStreamNonBlocking);
        cudaStreamCreateWithFlags(&s3, cudaStreamNonBlocking);
        cudaEventCreateWithFlags(&eFork, cudaEventDisableTiming);
        cudaEventCreateWithFlags(&evHid, cudaEventDisableTiming);
        cudaEventCreateWithFlags(&evScan, cudaEventDisableTiming);
        cudaEventCreateWithFlags(&e1, cudaEventDisableTiming);
        cudaEventCreateWithFlags(&e2, cudaEventDisableTiming);
        cudaEventCreateWithFlags(&e3, cudaEventDisableTiming);
        init_done = true;
    }

    // ---- fork origin: side streams must join capture BEFORE any launch ----
    cudaEventRecord(eFork, 0);
    cudaStreamWaitEvent(s1, eFork, 0);
    cudaStreamWaitEvent(s2, eFork, 0);
    cudaStreamWaitEvent(s3, eFork, 0);

    // ---- scan FIRST (s3) so evScan is recorded before any wait on it ------
    scan_targets_kernel<<<1, 1024, 0, s3>>>(targets);
    cudaEventRecord(evScan, s3);

    // ---- stream 0: hidden hi/lo conversion (shared by all branches) -------
    conv_pair_kernel<<<1024, 256>>>((const float4*)hidden, hidh, hidl, BATCH * HDIM / 4);
    cudaEventRecord(evHid, 0);

    // ---- branch 2 (s2): down0+emb0 convs -> dec0 -> h0 -> out0 ------------
    conv_hi_kernel<<<256, 256, 0, s2>>>((const float4*)down0, d0h, HDIM * HDIM / 4);
    conv_hi_kernel<<<1024, 256, 0, s2>>>((const float4*)(embed + (size_t)CUT0 * HDIM),
                                         embh + (size_t)CUT0 * HDIM, NCOLS0 * HDIM / 4);
    hmma_gemm_kernel<<<dim3(8, 141), 256, SMEM_BYTES, s2>>>(
        embh + (size_t)CUT0 * HDIM, nullptr, nullptr,
        d0h, HDIM, HDIM,
        nullptr, 0, 0, HDIM, nullptr, dec0h, NCOLS0, 0);
    cudaStreamWaitEvent(s2, evHid, 0);
    cudaStreamWaitEvent(s2, evScan, 0);
    hmma_gemm_kernel<<<dim3(8, 64), 256, SMEM_BYTES, s2>>>(
        hidh, hidl, idx0, d0h, HDIM, HDIM,
        nullptr, 0, 0, HDIM, nullptr, h0h, 0, 1);
    hmma_gemm_kernel<<<dim3(141, 64), 256, SMEM_BYTES, s2>>>(
        h0h, nullptr, nullptr, dec0h, NCOLS0, HDIM,
        out, (long long)BATCH * HEADC, 0, NCOLS0, bias0, nullptr, 0, 1);
    cudaEventRecord(e2, s2);

    // ---- branch 3 (s3): down1+emb1 convs -> dec1 -> h1 -> out1 ------------
    conv_hi_kernel<<<128, 256, 0, s3>>>((const float4*)down1, d1h, H4 * HDIM / 4);
    conv_hi_kernel<<<1024, 256, 0, s3>>>((const float4*)(embed + (size_t)CUT1 * HDIM),
                                         embh + (size_t)CUT1 * HDIM, NCOLS1 * HDIM / 4);
    hmma_gemm_kernel<<<dim3(2, 235), 256, SMEM_BYTES, s3>>>(
        embh + (size_t)CUT1 * HDIM, nullptr, nullptr,
        d1h, H4, HDIM,
        nullptr, 0, 0, H4, nullptr, dec1h, NCOLS1, 0);
    cudaStreamWaitEvent(s3, evHid, 0);
    hmma_gemm_kernel<<<dim3(2, 64), 256, SMEM_BYTES, s3>>>(
        hidh, hidl, idx1, d1h, H4, HDIM,
        nullptr, 0, 0, H4, nullptr, h1h, 0, 2);
    hmma_gemm_kernel<<<dim3(235, 64), 256, SMEM_BYTES, s3>>>(
        h1h, nullptr, nullptr, dec1h, NCOLS1, H4,
        out, (long long)BATCH * HEADC, 1, NCOLS1, bias1, nullptr, 0, 2);
    cudaEventRecord(e3, s3);

    // ---- branch 1 (s1): emb-head conv -> head (1-pass) --------------------
    conv_hi_kernel<<<512, 256, 0, s1>>>((const float4*)embed, embh, CUT0 * HDIM / 4);
    cudaStreamWaitEvent(s1, evHid, 0);
    hmma_gemm_kernel<<<dim3(16, 64), 256, SMEM_BYTES, s1>>>(
        hidh, nullptr, nullptr, embh, CUT0, HDIM,
        out, 0, 0, HEADC, sbias, nullptr, BATCH, 0);
    head_tail_kernel<<<BATCH / 4, 128, 0, s1>>>(hidden, tailW, tailb, out);
    cudaEventRecord(e1, s1);

    // ---- join back to capture stream --------------------------------------
    cudaStreamWaitEvent(0, e1, 0);
    cudaStreamWaitEvent(0, e2, 0);
    cudaStreamWaitEvent(0, e3, 0);
}

// round 17
// speedup vs baseline: 1.3199x; 1.3199x over previous
#include <cuda_runtime.h>
#include <cuda_fp16.h>
#include <cstdint>

#define CUT0   2000
#define CUT1   20000
#define BATCH  8192
#define HDIM   1024
#define H4     256
#define NCOLS0 18000
#define NCOLS1 30000
#define HEADC  2002

#define BM 128
#define BN 128
#define BK 32
#define LDS 40                 // halves per smem row (32 + 8 pad)
#define OPBYTES 10240          // 128*40*2
#define BUFBYTES 20480         // 2 operand tiles (Ah, Bh)
#define NSTAGE 4
#define SMEM_BYTES 81920       // 4 stages; 2 CTAs/SM -> 163840 <= 228KB

// ---------------- device scratch (no allocations allowed) ----------------
__device__ int d_idx0[BATCH];
__device__ int d_idx1[BATCH];
__device__ int d_counts[2];

__device__ __half g_hidh[BATCH * HDIM];
__device__ __half g_embh[50000 * HDIM];
__device__ __half g_d0h[HDIM * HDIM];
__device__ __half g_d1h[H4 * HDIM];
__device__ __half g_dec0h[NCOLS0 * HDIM];
__device__ __half g_dec1h[NCOLS1 * H4];
__device__ __half g_h0h[BATCH * HDIM];
__device__ __half g_h1h[BATCH * H4];

// ---------------- PTX helpers --------------------------------------------
__device__ __forceinline__ uint32_t smem_u32(const void* p) {
    uint32_t a;
    asm("{ .reg .u64 t; cvta.to.shared.u64 t, %1; cvt.u32.u64 %0, t; }"
        : "=r"(a) : "l"(p));
    return a;
}
#define CPA(dst, src) \
    asm volatile("cp.async.cg.shared.global [%0], [%1], 16;" \
                 :: "r"(dst), "l"(src) : "memory")
#define CPA_COMMIT() asm volatile("cp.async.commit_group;" ::: "memory")
#define CPA_WAIT(n)  asm volatile("cp.async.wait_group %0;" :: "n"(n) : "memory")

#define LDSM4(r, addr) \
    asm volatile("ldmatrix.sync.aligned.m8n8.x4.shared.b16 {%0,%1,%2,%3}, [%4];" \
                 : "=r"((r)[0]), "=r"((r)[1]), "=r"((r)[2]), "=r"((r)[3]) \
                 : "r"(addr))

#define MMA_FP16(c, a, b0, b1) \
    asm volatile("mma.sync.aligned.m16n8k16.row.col.f32.f16.f16.f32 " \
                 "{%0,%1,%2,%3}, {%4,%5,%6,%7}, {%8,%9}, {%0,%1,%2,%3};" \
                 : "+f"((c)[0]), "+f"((c)[1]), "+f"((c)[2]), "+f"((c)[3]) \
                 : "r"((a)[0]), "r"((a)[1]), "r"((a)[2]), "r"((a)[3]), \
                   "r"(b0), "r"(b1))

// ---------------- partition targets (int32/int64 agnostic) ---------------
__global__ void scan_targets_kernel(const int* __restrict__ tw) {
    __shared__ int s0[1024], s1[1024];
    __shared__ int anynz;
    int t = threadIdx.x;
    if (t == 0) anynz = 0;
    __syncthreads();
    int nz = 0;
    for (int i = t; i < 4096; i += 1024) nz |= (tw[2 * i + 1] != 0);
    if (nz) atomicOr(&anynz, 1);
    __syncthreads();
    int stride = anynz ? 1 : 2;

    int v[8]; int c0 = 0, c1 = 0;
#pragma unroll
    for (int i = 0; i < 8; i++) {
        v[i] = tw[(t * 8 + i) * stride];
        c0 += (v[i] >= CUT0 && v[i] < CUT1) ? 1 : 0;
        c1 += (v[i] >= CUT1) ? 1 : 0;
    }
    s0[t] = c0; s1[t] = c1;
    __syncthreads();
    for (int off = 1; off < 1024; off <<= 1) {
        int a0 = (t >= off) ? s0[t - off] : 0;
        int a1 = (t >= off) ? s1[t - off] : 0;
        __syncthreads();
        s0[t] += a0; s1[t] += a1;
        __syncthreads();
    }
    int p0 = s0[t] - c0, p1 = s1[t] - c1;
#pragma unroll
    for (int i = 0; i < 8; i++) {
        if (v[i] >= CUT0 && v[i] < CUT1)      d_idx0[p0++] = t * 8 + i;
        else if (v[i] >= CUT1)                d_idx1[p1++] = t * 8 + i;
    }
    if (t == 1023) { d_counts[0] = s0[1023]; d_counts[1] = s1[1023]; }
}

// ---------------- fp32 -> fp16 conversion ---------------------------------
__global__ void conv_hi_kernel(const float4* __restrict__ src,
                               __half* __restrict__ hi, int n4) {
    int i = blockIdx.x * blockDim.x + threadIdx.x;
    int stride = gridDim.x * blockDim.x;
    for (; i < n4; i += stride) {
        float4 v = src[i];
        __half2* ph = (__half2*)(hi + (size_t)i * 4);
        ph[0] = __halves2half2(__float2half(v.x), __float2half(v.y));
        ph[1] = __halves2half2(__float2half(v.z), __float2half(v.w));
    }
}

// ---------------- HMMA fp16 GEMM: C = fp16(A) @ fp16(B)^T (+bias) --------
// CTA tile 128x128xBK32, 256 threads, warps 4(M)x2(N), warp tile 32x64.
// 4-stage cp.async pipeline, ONE syncthreads per K-chunk.
__global__ void __launch_bounds__(256, 2) hmma_gemm_kernel(
    const __half* __restrict__ Ah,
    const int* __restrict__ rowidx,
    const __half* __restrict__ Bh,
    int N, int K,
    float* __restrict__ Cf, long long coff, int add_n0_off, int ldc,
    const float* __restrict__ bias,
    __half* __restrict__ Chi,
    int Mstatic, int msel)
{
    int M = (msel == 0) ? Mstatic : d_counts[msel - 1];
    int brow0 = blockIdx.y * BM;
    if (brow0 >= M) return;
    int bcol0 = blockIdx.x * BN;

    extern __shared__ char smem[];
    uint32_t sbase = smem_u32(smem);
    int tid = threadIdx.x, lane = tid & 31, wid = tid >> 5;
    int m0w = (wid >> 1) * 32, n0w = (wid & 1) * 64;

    // ---- gmem load plan: 2 units/thread per operand ----------------------
    int u1 = tid, u2 = tid + 256;
    int r1 = u1 >> 2, kq1 = u1 & 3, r2 = u2 >> 2, kq2 = u2 & 3;
    int ga1 = brow0 + r1; if (ga1 >= M) ga1 = M - 1;
    int ga2 = brow0 + r2; if (ga2 >= M) ga2 = M - 1;
    if (rowidx) { ga1 = rowidx[ga1]; ga2 = rowidx[ga2]; }
    int gb1 = bcol0 + r1; if (gb1 >= N) gb1 = N - 1;
    int gb2 = bcol0 + r2; if (gb2 >= N) gb2 = N - 1;
    const __half* pA1 = Ah + (size_t)ga1 * K + kq1 * 8;
    const __half* pB1 = Bh + (size_t)gb1 * K + kq1 * 8;
    const __half* pA2 = Ah + (size_t)ga2 * K + kq2 * 8;
    const __half* pB2 = Bh + (size_t)gb2 * K + kq2 * 8;
    uint32_t sm1 = (uint32_t)(r1 * LDS + kq1 * 8) * 2;
    uint32_t sm2 = (uint32_t)(r2 * LDS + kq2 * 8) * 2;

    float acc[2][8][4];
#pragma unroll
    for (int mi = 0; mi < 2; mi++)
#pragma unroll
        for (int nf = 0; nf < 8; nf++)
#pragma unroll
            for (int e = 0; e < 4; e++) acc[mi][nf][e] = 0.f;

    int NCk = K >> 5;

#define ISSUE_STAGE(st, k0)                                                    \
    do {                                                                       \
        uint32_t b_ = sbase + (uint32_t)(st) * BUFBYTES;                       \
        CPA(b_ + sm1,           pA1 + (k0));                                   \
        CPA(b_ + sm2,           pA2 + (k0));                                   \
        CPA(b_ + OPBYTES + sm1, pB1 + (k0));                                   \
        CPA(b_ + OPBYTES + sm2, pB2 + (k0));                                   \
        CPA_COMMIT();                                                          \
    } while (0)

    ISSUE_STAGE(0, 0);
    if (NCk > 1) ISSUE_STAGE(1, BK);
    if (NCk > 2) ISSUE_STAGE(2, 2 * BK);

    int lrow = lane & 15, lk = (lane >> 4) * 8;

    for (int c = 0; c < NCk; c++) {
        // wait for stage c; leave up to min(2, NCk-c-1) groups in flight
        if (c <= NCk - 3)      { CPA_WAIT(2); }
        else if (c == NCk - 2) { CPA_WAIT(1); }
        else                   { CPA_WAIT(0); }
        __syncthreads();   // stage c visible; buffer (c+3)%4 fully consumed
        if (c + 3 <= NCk - 1) ISSUE_STAGE((c + 3) % NSTAGE, (c + 3) * BK);

        uint32_t buf = sbase + (uint32_t)(c % NSTAGE) * BUFBYTES;
#pragma unroll
        for (int ki = 0; ki < 2; ki++) {
            uint32_t koffb = (uint32_t)(ki * 16 + lk) * 2;
            uint32_t ah[2][4];
#pragma unroll
            for (int mi = 0; mi < 2; mi++) {
                uint32_t ro = (uint32_t)((m0w + mi * 16 + lrow) * LDS) * 2 + koffb;
                LDSM4(ah[mi], buf + ro);
            }
#pragma unroll
            for (int np = 0; np < 4; np++) {
                uint32_t ro = (uint32_t)((n0w + np * 16 + lrow) * LDS) * 2 + koffb;
                uint32_t bh[4];
                LDSM4(bh, buf + OPBYTES + ro);
#pragma unroll
                for (int mi = 0; mi < 2; mi++) {
                    MMA_FP16(acc[mi][np * 2],     ah[mi], bh[0], bh[2]);
                    MMA_FP16(acc[mi][np * 2 + 1], ah[mi], bh[1], bh[3]);
                }
            }
        }
    }
    __syncthreads();

    // ---- epilogue ---------------------------------------------------------
    float* Cdst = Cf ? (Cf + coff +
        (add_n0_off ? (long long)d_counts[0] * (long long)NCOLS0 : 0ll)) : nullptr;
#pragma unroll
    for (int mi = 0; mi < 2; mi++) {
        int m = brow0 + m0w + mi * 16 + (lane >> 2);
#pragma unroll
        for (int nf = 0; nf < 8; nf++) {
            int n = bcol0 + n0w + nf * 8 + (lane & 3) * 2;
            if (n >= N) continue;
            float v0 = acc[mi][nf][0], v1 = acc[mi][nf][1];
            float v2 = acc[mi][nf][2], v3 = acc[mi][nf][3];
            if (Cdst) {
                float b0 = bias ? bias[n] : 0.f, b1 = bias ? bias[n + 1] : 0.f;
                if (m < M)
                    *(float2*)(Cdst + (size_t)m * ldc + n) = make_float2(v0 + b0, v1 + b1);
                if (m + 8 < M)
                    *(float2*)(Cdst + (size_t)(m + 8) * ldc + n) = make_float2(v2 + b0, v3 + b1);
            } else {
                if (m < M)
                    *(__half2*)(Chi + (size_t)m * ldc + n) =
                        __halves2half2(__float2half(v0), __float2half(v1));
                if (m + 8 < M)
                    *(__half2*)(Chi + (size_t)(m + 8) * ldc + n) =
                        __halves2half2(__float2half(v2), __float2half(v3));
            }
        }
    }
}

// -------- head tail columns: out[:, 2000:2002] ----------------------------
__global__ void head_tail_kernel(const float* __restrict__ hidden,
                                 const float* __restrict__ tw,
                                 const float* __restrict__ tb,
                                 float* __restrict__ out) {
    int row  = blockIdx.x * 4 + (threadIdx.x >> 5);
    int lane = threadIdx.x & 31;
    const float* h = hidden + (size_t)row * HDIM;
    float s0 = 0.f, s1 = 0.f;
    for (int i = lane; i < HDIM; i += 32) {
        float x = h[i];
        s0 += x * tw[i];
        s1 += x * tw[HDIM + i];
    }
#pragma unroll
    for (int o = 16; o > 0; o >>= 1) {
        s0 += __shfl_xor_sync(0xffffffffu, s0, o);
        s1 += __shfl_xor_sync(0xffffffffu, s1, o);
    }
    if (lane == 0) {
        out[(size_t)row * HEADC + CUT0]     = s0 + tb[0];
        out[(size_t)row * HEADC + CUT0 + 1] = s1 + tb[1];
    }
}

extern "C" void kernel_launch(void* const* d_in, const int* in_sizes, int n_in,
                              void* d_out, int out_size)
{
    (void)in_sizes; (void)n_in; (void)out_size;
    const float* hidden = (const float*)d_in[0];
    const float* embed  = (const float*)d_in[1];
    const float* tailW  = (const float*)d_in[2];
    const float* tailb  = (const float*)d_in[3];
    const float* sbias  = (const float*)d_in[4];
    const float* bias0  = (const float*)d_in[5];
    const float* bias1  = (const float*)d_in[6];
    const float* down0  = (const float*)d_in[7];
    const float* down1  = (const float*)d_in[8];
    const int*   targets = (const int*)d_in[9];
    float* out = (float*)d_out;

    __half *hidh, *embh, *d0h, *d1h;
    __half *dec0h, *dec1h, *h0h, *h1h;
    int *idx0, *idx1;
    cudaGetSymbolAddress((void**)&hidh, g_hidh);
    cudaGetSymbolAddress((void**)&embh, g_embh);
    cudaGetSymbolAddress((void**)&d0h, g_d0h);    cudaGetSymbolAddress((void**)&d1h, g_d1h);
    cudaGetSymbolAddress((void**)&dec0h, g_dec0h); cudaGetSymbolAddress((void**)&dec1h, g_dec1h);
    cudaGetSymbolAddress((void**)&h0h, g_h0h);    cudaGetSymbolAddress((void**)&h1h, g_h1h);
    cudaGetSymbolAddress((void**)&idx0, d_idx0);  cudaGetSymbolAddress((void**)&idx1, d_idx1);

    static bool init_done = false;
    static cudaStream_t s1, s2, s3;
    static cudaEvent_t eFork, evHid, evScan, e1, e2, e3;
    if (!init_done) {
        cudaFuncSetAttribute(hmma_gemm_kernel,
                             cudaFuncAttributeMaxDynamicSharedMemorySize, SMEM_BYTES);
        cudaStreamCreateWithFlags(&s1, cudaStreamNonBlocking);
        cudaStreamCreateWithFlags(&s2, cudaStreamNonBlocking);
        cudaStreamCreateWithFlags(&s3, cudaStreamNonBlocking);
        cudaEventCreateWithFlags(&eFork, cudaEventDisableTiming);
        cudaEventCreateWithFlags(&evHid, cudaEventDisableTiming);
        cudaEventCreateWithFlags(&evScan, cudaEventDisableTiming);
        cudaEventCreateWithFlags(&e1, cudaEventDisableTiming);
        cudaEventCreateWithFlags(&e2, cudaEventDisableTiming);
        cudaEventCreateWithFlags(&e3, cudaEventDisableTiming);
        init_done = true;
    }

    // ---- fork origin: side streams must join capture BEFORE any launch ----
    cudaEventRecord(eFork, 0);
    cudaStreamWaitEvent(s1, eFork, 0);
    cudaStreamWaitEvent(s2, eFork, 0);
    cudaStreamWaitEvent(s3, eFork, 0);

    // ---- scan FIRST (s3) so evScan is recorded before any wait on it ------
    scan_targets_kernel<<<1, 1024, 0, s3>>>(targets);
    cudaEventRecord(evScan, s3);

    // ---- stream 0: hidden fp16 conversion (shared by all branches) --------
    conv_hi_kernel<<<1024, 256>>>((const float4*)hidden, hidh, BATCH * HDIM / 4);
    cudaEventRecord(evHid, 0);

    // ---- branch 2 (s2): down0+emb0 convs -> dec0 -> h0 -> out0 ------------
    conv_hi_kernel<<<256, 256, 0, s2>>>((const float4*)down0, d0h, HDIM * HDIM / 4);
    conv_hi_kernel<<<1024, 256, 0, s2>>>((const float4*)(embed + (size_t)CUT0 * HDIM),
                                         embh + (size_t)CUT0 * HDIM, NCOLS0 * HDIM / 4);
    hmma_gemm_kernel<<<dim3(8, 141), 256, SMEM_BYTES, s2>>>(
        embh + (size_t)CUT0 * HDIM, nullptr, d0h, HDIM, HDIM,
        nullptr, 0, 0, HDIM, nullptr, dec0h, NCOLS0, 0);
    cudaStreamWaitEvent(s2, evHid, 0);
    cudaStreamWaitEvent(s2, evScan, 0);
    hmma_gemm_kernel<<<dim3(8, 64), 256, SMEM_BYTES, s2>>>(
        hidh, idx0, d0h, HDIM, HDIM,
        nullptr, 0, 0, HDIM, nullptr, h0h, 0, 1);
    hmma_gemm_kernel<<<dim3(141, 64), 256, SMEM_BYTES, s2>>>(
        h0h, nullptr, dec0h, NCOLS0, HDIM,
        out, (long long)BATCH * HEADC, 0, NCOLS0, bias0, nullptr, 0, 1);
    cudaEventRecord(e2, s2);

    // ---- branch 3 (s3): down1+emb1 convs -> dec1 -> h1 -> out1 ------------
    conv_hi_kernel<<<128, 256, 0, s3>>>((const float4*)down1, d1h, H4 * HDIM / 4);
    conv_hi_kernel<<<1024, 256, 0, s3>>>((const float4*)(embed + (size_t)CUT1 * HDIM),
                                         embh + (size_t)CUT1 * HDIM, NCOLS1 * HDIM / 4);
    hmma_gemm_kernel<<<dim3(2, 235), 256, SMEM_BYTES, s3>>>(
        embh + (size_t)CUT1 * HDIM, nullptr, d1h, H4, HDIM,
        nullptr, 0, 0, H4, nullptr, dec1h, NCOLS1, 0);
    cudaStreamWaitEvent(s3, evHid, 0);
    hmma_gemm_kernel<<<dim3(2, 64), 256, SMEM_BYTES, s3>>>(
        hidh, idx1, d1h, H4, HDIM,
        nullptr, 0, 0, H4, nullptr, h1h, 0, 2);
    hmma_gemm_kernel<<<dim3(235, 64), 256, SMEM_BYTES, s3>>>(
        h1h, nullptr, dec1h, NCOLS1, H4,
        out, (long long)BATCH * HEADC, 1, NCOLS1, bias1, nullptr, 0, 2);
    cudaEventRecord(e3, s3);

    // ---- branch 1 (s1): emb-head conv -> head -----------------------------
    conv_hi_kernel<<<512, 256, 0, s1>>>((const float4*)embed, embh, CUT0 * HDIM / 4);
    cudaStreamWaitEvent(s1, evHid, 0);
    hmma_gemm_kernel<<<dim3(16, 64), 256, SMEM_BYTES, s1>>>(
        hidh, nullptr, embh, CUT0, HDIM,
        out, 0, 0, HEADC, sbias, nullptr, BATCH, 0);
    head_tail_kernel<<<BATCH / 4, 128, 0, s1>>>(hidden, tailW, tailb, out);
    cudaEventRecord(e1, s1);

    // ---- join back to capture stream --------------------------------------
    cudaStreamWaitEvent(0, e1, 0);
    cudaStreamWaitEvent(0, e2, 0);
    cudaStreamWaitEvent(0, e3, 0);
}